// round 6
// baseline (speedup 1.0000x reference)
#include <cuda_runtime.h>
#include <cuda_bf16.h>

// Problem constants (fixed shapes)
constexpr int QN = 16;      // query rows
constexpr int D  = 384;     // embedding dim
constexpr int NV = D / 4;   // float4 per row
constexpr int N  = 50000;   // corpus docs
constexpr int TOTAL = QN * N;
constexpr int NBIN = 65536; // 16-bit sim-order buckets per row

constexpr int PBT = 1024;            // threads in pav_bucket block
constexpr int BPT = NBIN / PBT;      // 64 bins per thread
constexpr int NMRG = 32;             // level-1 mergers
constexpr int LPM  = PBT / NMRG;     // 32 thread-lists per merger
constexpr int MCAP = LPM * BPT;      // 2048 bucket cap per merger list

constexpr double FXS = 4398046511104.0;   // 2^42 fixed-point scale

// ---------------- static device scratch (no allocations allowed) ------------
__device__ unsigned           g_cnt[QN * NBIN];    // bucket counts
__device__ unsigned long long g_zsum[QN * NBIN];   // bucket sum(z) fixed-point
__device__ unsigned           g_pref[QN * NBIN];   // row-local exclusive prefix

__device__ double g_asum[QN * PBT * BPT];  // phase-A per-thread lists
__device__ int    g_acnt[QN * PBT * BPT];
__device__ int    g_anb[QN * PBT];

__device__ double g_m1s[QN * NMRG * MCAP]; // level-1 merged lists
__device__ int    g_m1c[QN * NMRG * MCAP];
__device__ int    g_m1n[QN * NMRG];

__device__ double g_fs[TOTAL];             // final block means
__device__ int    g_fc[TOTAL];
__device__ int    g_fe[TOTAL];             // final block ends (element positions)
__device__ int    g_B[QN];                 // final block counts

__device__ __forceinline__ unsigned ord_of(unsigned u) {
    return u ^ ((u & 0x80000000u) ? 0xFFFFFFFFu : 0x80000000u);
}

// ---------------- sims + bucket aggregation ----------------------------------
// Persistent blocks: stage+normalize q once, then warps loop over docs.
__global__ __launch_bounds__(256) void sim_kernel(
    const float* __restrict__ qg, const float* __restrict__ cg,
    float* __restrict__ sims, unsigned* __restrict__ cnt,
    unsigned long long* __restrict__ zsum)
{
    __shared__ float4 qsh[QN * NV];   // 24 KB
    __shared__ float qinv[QN];
    int tid = threadIdx.x;

    for (int i = tid; i < QN * NV; i += 256)
        qsh[i] = reinterpret_cast<const float4*>(qg)[i];
    __syncthreads();
    if (tid < QN) {
        float ss = 0.f;
        const float4* row = qsh + tid * NV;
        #pragma unroll 8
        for (int j = 0; j < NV; j++) {
            float4 v = row[j];
            ss += v.x*v.x + v.y*v.y + v.z*v.z + v.w*v.w;
        }
        qinv[tid] = 1.0f / fmaxf(sqrtf(ss), 1e-12f);
    }
    __syncthreads();
    for (int i = tid; i < QN * NV; i += 256) {
        float s = qinv[i / NV];
        float4 v = qsh[i];
        v.x *= s; v.y *= s; v.z *= s; v.w *= s;
        qsh[i] = v;
    }
    __syncthreads();

    const int warp = tid >> 5, lane = tid & 31;
    const int gw = blockIdx.x * 8 + warp;
    const int NW = gridDim.x * 8;

    for (int doc = gw; doc < N; doc += NW) {
        const float4* cp = reinterpret_cast<const float4*>(cg + (size_t)doc * D);
        float4 cv[3];
        #pragma unroll
        for (int j = 0; j < 3; j++) cv[j] = cp[lane + 32 * j];

        float ss = 0.f;
        #pragma unroll
        for (int j = 0; j < 3; j++)
            ss += cv[j].x*cv[j].x + cv[j].y*cv[j].y + cv[j].z*cv[j].z + cv[j].w*cv[j].w;

        float acc[QN];
        #pragma unroll
        for (int r = 0; r < QN; r++) {
            float a = 0.f;
            #pragma unroll
            for (int j = 0; j < 3; j++) {
                float4 qv = qsh[r * NV + lane + 32 * j];
                a += qv.x*cv[j].x + qv.y*cv[j].y + qv.z*cv[j].z + qv.w*cv[j].w;
            }
            acc[r] = a;
        }
        #pragma unroll
        for (int o = 16; o; o >>= 1) {
            ss += __shfl_xor_sync(0xFFFFFFFFu, ss, o);
            #pragma unroll
            for (int r = 0; r < QN; r++)
                acc[r] += __shfl_xor_sync(0xFFFFFFFFu, acc[r], o);
        }
        if (lane == 0) {
            float cinv = 1.0f / fmaxf(sqrtf(ss), 1e-12f);
            #pragma unroll
            for (int r = 0; r < QN; r++) {
                float sim = acc[r] * cinv;
                int gi = r * N + doc;
                sims[gi] = sim;
                unsigned u = __float_as_uint(sim);
                unsigned bin = (unsigned)(r << 16) | (ord_of(u) >> 16);
                atomicAdd(&cnt[bin], 1u);
                long long q = __double2ll_rn((double)sim * -10.0 * FXS);
                atomicAdd(&zsum[bin], (unsigned long long)q);
            }
        }
    }
}

// ---------------- fused bucket PAV: scan + local PAV + 2-level merge ---------
// One block per row, 1024 threads, 64 contiguous bins each.
// Bucket b at start position p with count c contributes pooled
// (sum = Sz - c*N + c*p + c*(c-1)/2, count = c); all exact in double.
__global__ __launch_bounds__(PBT) void pav_bucket_kernel(
    const unsigned* __restrict__ cnt, const unsigned long long* __restrict__ zsum,
    unsigned* __restrict__ pref)
{
    const int row = blockIdx.x;
    const int t = threadIdx.x;
    const int b0 = row * NBIN + t * BPT;

    // Vectorized load of this thread's 64 bucket counts
    unsigned lcnt[BPT];
    {
        const uint4* p4 = reinterpret_cast<const uint4*>(cnt + b0);
        #pragma unroll
        for (int j = 0; j < BPT / 4; j++) {
            uint4 v = p4[j];
            lcnt[j*4+0] = v.x; lcnt[j*4+1] = v.y;
            lcnt[j*4+2] = v.z; lcnt[j*4+3] = v.w;
        }
    }
    unsigned tsum = 0;
    #pragma unroll
    for (int j = 0; j < BPT; j++) tsum += lcnt[j];

    // Block-wide exclusive scan of per-thread sums
    __shared__ unsigned s[PBT];
    s[t] = tsum;
    __syncthreads();
    #pragma unroll
    for (int off = 1; off < PBT; off <<= 1) {
        unsigned v = (t >= off) ? s[t - off] : 0u;
        __syncthreads();
        s[t] += v;
        __syncthreads();
    }
    unsigned texcl = s[t] - tsum;

    // Write per-bin prefixes (vectorized) and run thread-local PAV
    double ls[BPT];
    int    lc[BPT];
    int nb = 0;
    {
        unsigned p = texcl;
        uint4* o4 = reinterpret_cast<uint4*>(pref + b0);
        #pragma unroll
        for (int j = 0; j < BPT / 4; j++) {
            uint4 w;
            w.x = p;               p += lcnt[j*4+0];
            w.y = p;               p += lcnt[j*4+1];
            w.z = p;               p += lcnt[j*4+2];
            w.w = p;               p += lcnt[j*4+3];
            o4[j] = w;
        }
        p = texcl;
        for (int j = 0; j < BPT; j++) {
            unsigned c = lcnt[j];
            if (c) {
                double zs = (double)(long long)zsum[b0 + j] * (1.0 / FXS);
                double dc = (double)c;
                double cs = zs - dc * (double)N + dc * (double)p
                            + 0.5 * dc * (double)(c - 1);
                int cc = (int)c;
                while (nb > 0 && ls[nb - 1] * (double)cc < cs * (double)lc[nb - 1]) {
                    cs += ls[nb - 1]; cc += lc[nb - 1]; nb--;
                }
                ls[nb] = cs; lc[nb] = cc; nb++;
            }
            p += c;
        }
    }
    const int ob = (row * PBT + t) * BPT;
    for (int b = 0; b < nb; b++) {
        g_asum[ob + b] = ls[b];
        g_acnt[ob + b] = lc[b];
    }
    g_anb[row * PBT + t] = nb;
    __syncthreads();

    // Level-1 merge: 32 mergers x 32 thread-lists
    if (t < NMRG) {
        const int mb = (row * NMRG + t) * MCAP;
        int B = 0;
        for (int tt = t * LPM; tt < t * LPM + LPM; tt++) {
            int nbt = g_anb[row * PBT + tt];
            const int bb = (row * PBT + tt) * BPT;
            for (int b = 0; b < nbt; b++) {
                double cs = g_asum[bb + b];
                int cc = g_acnt[bb + b];
                while (B > 0 && g_m1s[mb + B - 1] * (double)cc < cs * (double)g_m1c[mb + B - 1]) {
                    cs += g_m1s[mb + B - 1]; cc += g_m1c[mb + B - 1]; B--;
                }
                g_m1s[mb + B] = cs; g_m1c[mb + B] = cc; B++;
            }
        }
        g_m1n[row * NMRG + t] = B;
    }
    __syncthreads();

    // Final merge + ends/means
    if (t == 0) {
        const int fb = row * N;
        int B = 0;
        for (int m = 0; m < NMRG; m++) {
            int nm = g_m1n[row * NMRG + m];
            const int mb = (row * NMRG + m) * MCAP;
            for (int b = 0; b < nm; b++) {
                double cs = g_m1s[mb + b];
                int cc = g_m1c[mb + b];
                while (B > 0 && g_fs[fb + B - 1] * (double)cc < cs * (double)g_fc[fb + B - 1]) {
                    cs += g_fs[fb + B - 1]; cc += g_fc[fb + B - 1]; B--;
                }
                g_fs[fb + B] = cs; g_fc[fb + B] = cc; B++;
            }
        }
        int e = 0;
        for (int b = 0; b < B; b++) {
            e += g_fc[fb + b];
            g_fe[fb + b] = e;
            g_fs[fb + b] = g_fs[fb + b] / (double)g_fc[fb + b];  // -> mean
        }
        g_B[row] = B;
    }
}

// ---------------- rank gather: fully coalesced -------------------------------
__global__ __launch_bounds__(256) void rank_kernel(
    const float* __restrict__ sims, const unsigned* __restrict__ pref,
    float* __restrict__ ranks)
{
    const int row = blockIdx.y;
    const int i = blockIdx.x * 256 + threadIdx.x;
    if (i >= N) return;
    const int gi = row * N + i;

    float sim = sims[gi];
    unsigned u = __float_as_uint(sim);
    unsigned bin = (unsigned)(row << 16) | (ord_of(u) >> 16);
    int p = (int)pref[bin];

    const int fb = row * N;
    int loB = 0, hiB = g_B[row];
    while (loB < hiB) {
        int mid = (loB + hiB) >> 1;
        if (g_fe[fb + mid] > p) hiB = mid; else loB = mid + 1;
    }
    ranks[gi] = (float)((double)sim * -10.0 - g_fs[fb + loB]);
}

// ---------------- launch -----------------------------------------------------
extern "C" void kernel_launch(void* const* d_in, const int* in_sizes, int n_in,
                              void* d_out, int out_size)
{
    const float* q = (const float*)d_in[0];
    const float* c = (const float*)d_in[1];
    float* out = (float*)d_out;
    float* sims = out;            // [QN*N]
    float* ranks = out + TOTAL;   // [QN*N]

    void *pc = nullptr, *pz = nullptr, *pp = nullptr;
    cudaGetSymbolAddress(&pc, g_cnt);
    cudaGetSymbolAddress(&pz, g_zsum);
    cudaGetSymbolAddress(&pp, g_pref);

    cudaMemsetAsync(pc, 0, QN * NBIN * sizeof(unsigned));
    cudaMemsetAsync(pz, 0, QN * NBIN * sizeof(unsigned long long));

    sim_kernel<<<200, 256>>>(q, c, sims, (unsigned*)pc,
                             (unsigned long long*)pz);
    pav_bucket_kernel<<<QN, PBT>>>((const unsigned*)pc,
                                   (const unsigned long long*)pz,
                                   (unsigned*)pp);
    dim3 gR((N + 255) / 256, QN);
    rank_kernel<<<gR, 256>>>(sims, (const unsigned*)pp, ranks);
}

// round 7
// speedup vs baseline: 3.3454x; 3.3454x over previous
#include <cuda_runtime.h>
#include <cuda_bf16.h>

// Problem constants (fixed shapes)
constexpr int QN = 16;      // query rows
constexpr int D  = 384;     // embedding dim
constexpr int NV = D / 4;   // float4 per row
constexpr int N  = 50000;   // corpus docs
constexpr int TOTAL = QN * N;
constexpr int BINBITS = 13;              // sign+8exp+4mant
constexpr int NBIN = 1 << BINBITS;       // 8192 buckets per row

constexpr int PBT = 1024;            // threads in pav_bucket block
constexpr int BPT = NBIN / PBT;      // 8 bins per thread
constexpr int NMRG = 32;             // level-1 mergers
constexpr int LPM  = PBT / NMRG;     // 32 thread-lists per merger
constexpr int MCAP = LPM * BPT;      // 256 bucket cap per merger list

constexpr double FXS = 4398046511104.0;   // 2^42 fixed-point scale (exact for z)

// ---------------- static device scratch (no allocations allowed) ------------
__device__ unsigned           g_cnt[QN * NBIN];    // bucket counts
__device__ unsigned long long g_zsum[QN * NBIN];   // bucket sum(z), fixed-point
__device__ unsigned           g_pref[QN * NBIN];   // row-local exclusive prefix

__device__ double g_asum[QN * PBT * BPT];  // phase-A per-thread lists
__device__ int    g_acnt[QN * PBT * BPT];
__device__ int    g_anb[QN * PBT];

__device__ double g_m1s[QN * NMRG * MCAP]; // level-1 merged lists
__device__ int    g_m1c[QN * NMRG * MCAP];
__device__ int    g_m1n[QN * NMRG];

__device__ double g_fs[QN * NBIN];         // final block means
__device__ int    g_fc[QN * NBIN];
__device__ int    g_fe[QN * NBIN];         // final block ends (element positions)
__device__ int    g_B[QN];                 // final block counts

__device__ __forceinline__ unsigned ord_of(unsigned u) {
    return u ^ ((u & 0x80000000u) ? 0xFFFFFFFFu : 0x80000000u);
}

// ---------------- sims only (lean GEMM, persistent blocks) -------------------
__global__ __launch_bounds__(256) void sim_kernel(
    const float* __restrict__ qg, const float* __restrict__ cg,
    float* __restrict__ sims)
{
    __shared__ float4 qsh[QN * NV];   // 24 KB
    __shared__ float qinv[QN];
    int tid = threadIdx.x;

    for (int i = tid; i < QN * NV; i += 256)
        qsh[i] = reinterpret_cast<const float4*>(qg)[i];
    __syncthreads();
    if (tid < QN) {
        float ss = 0.f;
        const float4* row = qsh + tid * NV;
        #pragma unroll 8
        for (int j = 0; j < NV; j++) {
            float4 v = row[j];
            ss += v.x*v.x + v.y*v.y + v.z*v.z + v.w*v.w;
        }
        qinv[tid] = 1.0f / fmaxf(sqrtf(ss), 1e-12f);
    }
    __syncthreads();
    for (int i = tid; i < QN * NV; i += 256) {
        float s = qinv[i / NV];
        float4 v = qsh[i];
        v.x *= s; v.y *= s; v.z *= s; v.w *= s;
        qsh[i] = v;
    }
    __syncthreads();

    const int warp = tid >> 5, lane = tid & 31;
    const int gw = blockIdx.x * 8 + warp;
    const int NW = gridDim.x * 8;

    for (int doc = gw; doc < N; doc += NW) {
        const float4* cp = reinterpret_cast<const float4*>(cg + (size_t)doc * D);
        float4 cv[3];
        #pragma unroll
        for (int j = 0; j < 3; j++) cv[j] = cp[lane + 32 * j];

        float ss = 0.f;
        #pragma unroll
        for (int j = 0; j < 3; j++)
            ss += cv[j].x*cv[j].x + cv[j].y*cv[j].y + cv[j].z*cv[j].z + cv[j].w*cv[j].w;

        float acc[QN];
        #pragma unroll
        for (int r = 0; r < QN; r++) {
            float a = 0.f;
            #pragma unroll
            for (int j = 0; j < 3; j++) {
                float4 qv = qsh[r * NV + lane + 32 * j];
                a += qv.x*cv[j].x + qv.y*cv[j].y + qv.z*cv[j].z + qv.w*cv[j].w;
            }
            acc[r] = a;
        }
        #pragma unroll
        for (int o = 16; o; o >>= 1) {
            ss += __shfl_xor_sync(0xFFFFFFFFu, ss, o);
            #pragma unroll
            for (int r = 0; r < QN; r++)
                acc[r] += __shfl_xor_sync(0xFFFFFFFFu, acc[r], o);
        }
        if (lane == 0) {
            float cinv = 1.0f / fmaxf(sqrtf(ss), 1e-12f);
            #pragma unroll
            for (int r = 0; r < QN; r++)
                sims[r * N + doc] = acc[r] * cinv;
        }
    }
}

// ---------------- bucket aggregation: lean full-occupancy pass ---------------
__global__ __launch_bounds__(512) void binagg_kernel(
    const float* __restrict__ sims, unsigned* __restrict__ cnt,
    unsigned long long* __restrict__ zsum)
{
    int gi = blockIdx.x * 512 + threadIdx.x;
    if (gi >= TOTAL) return;
    float sim = sims[gi];
    int row = gi / N;
    unsigned u = __float_as_uint(sim);
    unsigned bin = ((unsigned)row << BINBITS) | (ord_of(u) >> (32 - BINBITS));
    atomicAdd(&cnt[bin], 1u);
    float z = sim * -10.0f;                       // matches reference fp32 z
    long long q = __double2ll_rn((double)z * FXS);  // exact (z has 24-bit mant)
    atomicAdd(&zsum[bin], (unsigned long long)q);
}

// ---------------- fused bucket PAV: scan + local PAV + 2-level merge ---------
// One block per row, 1024 threads, 8 contiguous bins each.
// Bucket at start position p with count c contributes pooled block
// (sum = Sz - c*N + c*p + c*(c-1)/2, count = c); exact in double.
__global__ __launch_bounds__(PBT) void pav_bucket_kernel(
    const unsigned* __restrict__ cnt, const unsigned long long* __restrict__ zsum,
    unsigned* __restrict__ pref)
{
    const int row = blockIdx.x;
    const int t = threadIdx.x;
    const int b0 = row * NBIN + t * BPT;

    unsigned lcnt[BPT];
    {
        const uint4* p4 = reinterpret_cast<const uint4*>(cnt + b0);
        #pragma unroll
        for (int j = 0; j < BPT / 4; j++) {
            uint4 v = p4[j];
            lcnt[j*4+0] = v.x; lcnt[j*4+1] = v.y;
            lcnt[j*4+2] = v.z; lcnt[j*4+3] = v.w;
        }
    }
    unsigned tsum = 0;
    #pragma unroll
    for (int j = 0; j < BPT; j++) tsum += lcnt[j];

    // Block-wide exclusive scan of per-thread sums
    __shared__ unsigned s[PBT];
    s[t] = tsum;
    __syncthreads();
    #pragma unroll
    for (int off = 1; off < PBT; off <<= 1) {
        unsigned v = (t >= off) ? s[t - off] : 0u;
        __syncthreads();
        s[t] += v;
        __syncthreads();
    }
    unsigned texcl = s[t] - tsum;

    // Per-bin prefixes + thread-local PAV over 8 buckets
    double ls[BPT];
    int    lc[BPT];
    int nb = 0;
    {
        unsigned p = texcl;
        uint4* o4 = reinterpret_cast<uint4*>(pref + b0);
        #pragma unroll
        for (int j = 0; j < BPT / 4; j++) {
            uint4 w;
            w.x = p; p += lcnt[j*4+0];
            w.y = p; p += lcnt[j*4+1];
            w.z = p; p += lcnt[j*4+2];
            w.w = p; p += lcnt[j*4+3];
            o4[j] = w;
        }
        p = texcl;
        #pragma unroll
        for (int j = 0; j < BPT; j++) {
            unsigned c = lcnt[j];
            if (c) {
                double zs = (double)(long long)zsum[b0 + j] * (1.0 / FXS);
                double dc = (double)c;
                double cs = zs - dc * (double)N + dc * (double)p
                            + 0.5 * dc * (double)(c - 1);
                int cc = (int)c;
                while (nb > 0 && ls[nb - 1] * (double)cc < cs * (double)lc[nb - 1]) {
                    cs += ls[nb - 1]; cc += lc[nb - 1]; nb--;
                }
                ls[nb] = cs; lc[nb] = cc; nb++;
            }
            p += c;
        }
    }
    const int ob = (row * PBT + t) * BPT;
    #pragma unroll
    for (int b = 0; b < BPT; b++) {
        if (b < nb) { g_asum[ob + b] = ls[b]; g_acnt[ob + b] = lc[b]; }
    }
    g_anb[row * PBT + t] = nb;
    __syncthreads();

    // Level-1 merge: 32 mergers x 32 thread-lists
    if (t < NMRG) {
        const int mb = (row * NMRG + t) * MCAP;
        int B = 0;
        for (int tt = t * LPM; tt < t * LPM + LPM; tt++) {
            int nbt = g_anb[row * PBT + tt];
            const int bb = (row * PBT + tt) * BPT;
            for (int b = 0; b < nbt; b++) {
                double cs = g_asum[bb + b];
                int cc = g_acnt[bb + b];
                while (B > 0 && g_m1s[mb + B - 1] * (double)cc < cs * (double)g_m1c[mb + B - 1]) {
                    cs += g_m1s[mb + B - 1]; cc += g_m1c[mb + B - 1]; B--;
                }
                g_m1s[mb + B] = cs; g_m1c[mb + B] = cc; B++;
            }
        }
        g_m1n[row * NMRG + t] = B;
    }
    __syncthreads();

    // Final merge + ends/means
    if (t == 0) {
        const int fb = row * NBIN;
        int B = 0;
        for (int m = 0; m < NMRG; m++) {
            int nm = g_m1n[row * NMRG + m];
            const int mb = (row * NMRG + m) * MCAP;
            for (int b = 0; b < nm; b++) {
                double cs = g_m1s[mb + b];
                int cc = g_m1c[mb + b];
                while (B > 0 && g_fs[fb + B - 1] * (double)cc < cs * (double)g_fc[fb + B - 1]) {
                    cs += g_fs[fb + B - 1]; cc += g_fc[fb + B - 1]; B--;
                }
                g_fs[fb + B] = cs; g_fc[fb + B] = cc; B++;
            }
        }
        int e = 0;
        for (int b = 0; b < B; b++) {
            e += g_fc[fb + b];
            g_fe[fb + b] = e;
            g_fs[fb + b] = g_fs[fb + b] / (double)g_fc[fb + b];  // -> mean
        }
        g_B[row] = B;
    }
}

// ---------------- rank gather: fully coalesced -------------------------------
__global__ __launch_bounds__(256) void rank_kernel(
    const float* __restrict__ sims, const unsigned* __restrict__ pref,
    float* __restrict__ ranks)
{
    const int row = blockIdx.y;
    const int i = blockIdx.x * 256 + threadIdx.x;
    if (i >= N) return;
    const int gi = row * N + i;

    float sim = sims[gi];
    unsigned u = __float_as_uint(sim);
    unsigned bin = ((unsigned)row << BINBITS) | (ord_of(u) >> (32 - BINBITS));
    int p = (int)pref[bin];

    const int fb = row * NBIN;
    int loB = 0, hiB = g_B[row];
    while (loB < hiB) {
        int mid = (loB + hiB) >> 1;
        if (g_fe[fb + mid] > p) hiB = mid; else loB = mid + 1;
    }
    float z = sim * -10.0f;
    ranks[gi] = (float)((double)z - g_fs[fb + loB]);
}

// ---------------- launch -----------------------------------------------------
extern "C" void kernel_launch(void* const* d_in, const int* in_sizes, int n_in,
                              void* d_out, int out_size)
{
    const float* q = (const float*)d_in[0];
    const float* c = (const float*)d_in[1];
    float* out = (float*)d_out;
    float* sims = out;            // [QN*N]
    float* ranks = out + TOTAL;   // [QN*N]

    void *pc = nullptr, *pz = nullptr, *pp = nullptr;
    cudaGetSymbolAddress(&pc, g_cnt);
    cudaGetSymbolAddress(&pz, g_zsum);
    cudaGetSymbolAddress(&pp, g_pref);

    cudaMemsetAsync(pc, 0, QN * NBIN * sizeof(unsigned));
    cudaMemsetAsync(pz, 0, QN * NBIN * sizeof(unsigned long long));

    sim_kernel<<<200, 256>>>(q, c, sims);
    binagg_kernel<<<(TOTAL + 511) / 512, 512>>>(sims, (unsigned*)pc,
                                                (unsigned long long*)pz);
    pav_bucket_kernel<<<QN, PBT>>>((const unsigned*)pc,
                                   (const unsigned long long*)pz,
                                   (unsigned*)pp);
    dim3 gR((N + 255) / 256, QN);
    rank_kernel<<<gR, 256>>>(sims, (const unsigned*)pp, ranks);
}

// round 10
// speedup vs baseline: 4.0684x; 1.2161x over previous
#include <cuda_runtime.h>
#include <cuda_bf16.h>

// Problem constants (fixed shapes)
constexpr int QN = 16;      // query rows
constexpr int D  = 384;     // embedding dim
constexpr int NV = D / 4;   // float4 per row
constexpr int N  = 50000;   // corpus docs
constexpr int TOTAL = QN * N;
constexpr int BINBITS = 13;              // sign+8exp+4mant
constexpr int NBIN = 1 << BINBITS;       // 8192 buckets per row

constexpr int PBT = 1024;            // threads in pav_bucket block
constexpr int BPT = NBIN / PBT;      // 8 bins per thread
constexpr int NMRG = 32;             // level-1 mergers
constexpr int LPM  = PBT / NMRG;     // 32 thread-lists per merger
constexpr int MCAP = LPM * BPT;      // 256 bucket cap per merger list

constexpr float FXS_F = 4398046511104.0f;  // 2^42 (exact; mul by it is exact)
constexpr double FXS = 4398046511104.0;

// ---------------- static device scratch (no allocations allowed) ------------
__device__ float              g_simt[TOTAL];      // transposed sims [doc][16]
__device__ unsigned           g_cnt[QN * NBIN];   // bucket counts
__device__ unsigned long long g_zsum[QN * NBIN];  // bucket sum(z), fixed-point
__device__ double             g_bmean[QN * NBIN]; // bucket -> its block mean

__device__ double g_asum[QN * PBT * BPT];  // phase-A per-thread lists
__device__ int    g_acnt[QN * PBT * BPT];
__device__ int    g_anb[QN * PBT];

__device__ double g_m1s[QN * NMRG * MCAP]; // level-1 merged lists
__device__ int    g_m1c[QN * NMRG * MCAP];
__device__ int    g_m1n[QN * NMRG];

__device__ double g_fs[QN * NBIN];         // final block means
__device__ int    g_fc[QN * NBIN];
__device__ int    g_fe[QN * NBIN];         // final block ends (element positions)
__device__ int    g_B[QN];                 // final block counts

__device__ __forceinline__ unsigned ord_of(unsigned u) {
    return u ^ ((u & 0x80000000u) ? 0xFFFFFFFFu : 0x80000000u);
}

// ---------------- sims + fused bucket aggregation ----------------------------
// Persistent blocks; warp-per-doc. 16 row-dots reduced via halving tree
// (16 shuffles) so lane 2r ends holding row r's full dot.
__global__ __launch_bounds__(256) void sim_kernel(
    const float* __restrict__ qg, const float* __restrict__ cg,
    float* __restrict__ simt, unsigned* __restrict__ cnt,
    unsigned long long* __restrict__ zsum)
{
    __shared__ float4 qsh[QN * NV];   // 24 KB
    __shared__ float qinv[QN];
    int tid = threadIdx.x;

    for (int i = tid; i < QN * NV; i += 256)
        qsh[i] = reinterpret_cast<const float4*>(qg)[i];
    __syncthreads();
    if (tid < QN) {
        float ss = 0.f;
        const float4* row = qsh + tid * NV;
        #pragma unroll 8
        for (int j = 0; j < NV; j++) {
            float4 v = row[j];
            ss += v.x*v.x + v.y*v.y + v.z*v.z + v.w*v.w;
        }
        qinv[tid] = 1.0f / fmaxf(sqrtf(ss), 1e-12f);
    }
    __syncthreads();
    for (int i = tid; i < QN * NV; i += 256) {
        float s = qinv[i / NV];
        float4 v = qsh[i];
        v.x *= s; v.y *= s; v.z *= s; v.w *= s;
        qsh[i] = v;
    }
    __syncthreads();

    const int warp = tid >> 5, lane = tid & 31;
    const int gw = blockIdx.x * 8 + warp;
    const int NW = gridDim.x * 8;

    for (int doc = gw; doc < N; doc += NW) {
        const float4* cp = reinterpret_cast<const float4*>(cg + (size_t)doc * D);
        float4 cv[3];
        #pragma unroll
        for (int j = 0; j < 3; j++) cv[j] = cp[lane + 32 * j];

        float ss = 0.f;
        #pragma unroll
        for (int j = 0; j < 3; j++)
            ss += cv[j].x*cv[j].x + cv[j].y*cv[j].y + cv[j].z*cv[j].z + cv[j].w*cv[j].w;

        float acc[QN];
        #pragma unroll
        for (int r = 0; r < QN; r++) {
            float a = 0.f;
            #pragma unroll
            for (int j = 0; j < 3; j++) {
                float4 qv = qsh[r * NV + lane + 32 * j];
                a += qv.x*cv[j].x + qv.y*cv[j].y + qv.z*cv[j].z + qv.w*cv[j].w;
            }
            acc[r] = a;
        }

        // self-dot: full butterfly (all lanes need it)
        #pragma unroll
        for (int o = 16; o; o >>= 1)
            ss += __shfl_xor_sync(0xFFFFFFFFu, ss, o);

        // halving-tree reduce of 16 accumulators: after the loop each lane
        // holds one row's partial pair-sum; final xor-1 completes it.
        // Resulting logical row = lane >> 1.
        #pragma unroll
        for (int off = 16; off >= 2; off >>= 1) {
            const int half = off >> 1;
            const bool up = (lane & off) != 0;
            #pragma unroll
            for (int r = 0; r < half; r++) {
                float send = up ? acc[r] : acc[r + half];
                float recv = __shfl_xor_sync(0xFFFFFFFFu, send, off);
                acc[r] = (up ? acc[r + half] : acc[r]) + recv;
            }
        }
        acc[0] += __shfl_xor_sync(0xFFFFFFFFu, acc[0], 1);

        if (!(lane & 1)) {
            const int r = lane >> 1;
            float cinv = 1.0f / fmaxf(sqrtf(ss), 1e-12f);
            float sim = acc[0] * cinv;
            simt[doc * QN + r] = sim;
            unsigned u = __float_as_uint(sim);
            unsigned bin = ((unsigned)r << BINBITS) | (ord_of(u) >> (32 - BINBITS));
            atomicAdd(&cnt[bin], 1u);
            float z = sim * -10.0f;
            long long q = __float2ll_rn(z * FXS_F);   // exact pow2 scale
            atomicAdd(&zsum[bin], (unsigned long long)q);
        }
    }
}

// ---------------- fused bucket PAV + bucket->mean map ------------------------
// One block per row, 1024 threads, 8 contiguous bins each. Bucket at start
// position p with count c pools into (sum = Sz - c*N + c*p + c*(c-1)/2, c).
__global__ __launch_bounds__(PBT) void pav_bucket_kernel(
    const unsigned* __restrict__ cnt, const unsigned long long* __restrict__ zsum,
    double* __restrict__ bmean)
{
    const int row = blockIdx.x;
    const int t = threadIdx.x;
    const int b0 = row * NBIN + t * BPT;

    unsigned lcnt[BPT];
    {
        const uint4* p4 = reinterpret_cast<const uint4*>(cnt + b0);
        #pragma unroll
        for (int j = 0; j < BPT / 4; j++) {
            uint4 v = p4[j];
            lcnt[j*4+0] = v.x; lcnt[j*4+1] = v.y;
            lcnt[j*4+2] = v.z; lcnt[j*4+3] = v.w;
        }
    }
    unsigned tsum = 0;
    #pragma unroll
    for (int j = 0; j < BPT; j++) tsum += lcnt[j];

    __shared__ unsigned s[PBT];
    s[t] = tsum;
    __syncthreads();
    #pragma unroll
    for (int off = 1; off < PBT; off <<= 1) {
        unsigned v = (t >= off) ? s[t - off] : 0u;
        __syncthreads();
        s[t] += v;
        __syncthreads();
    }
    unsigned texcl = s[t] - tsum;

    // per-bin start positions + thread-local PAV over 8 buckets
    unsigned lpre[BPT];
    double ls[BPT];
    int    lc[BPT];
    int nb = 0;
    {
        unsigned p = texcl;
        #pragma unroll
        for (int j = 0; j < BPT; j++) {
            lpre[j] = p;
            unsigned c = lcnt[j];
            if (c) {
                double zs = (double)(long long)zsum[b0 + j] * (1.0 / FXS);
                double dc = (double)c;
                double cs = zs - dc * (double)N + dc * (double)p
                            + 0.5 * dc * (double)(c - 1);
                int cc = (int)c;
                while (nb > 0 && ls[nb - 1] * (double)cc < cs * (double)lc[nb - 1]) {
                    cs += ls[nb - 1]; cc += lc[nb - 1]; nb--;
                }
                ls[nb] = cs; lc[nb] = cc; nb++;
            }
            p += c;
        }
    }
    const int ob = (row * PBT + t) * BPT;
    #pragma unroll
    for (int b = 0; b < BPT; b++) {
        if (b < nb) { g_asum[ob + b] = ls[b]; g_acnt[ob + b] = lc[b]; }
    }
    g_anb[row * PBT + t] = nb;
    __syncthreads();

    // Level-1 merge: 32 mergers x 32 thread-lists
    if (t < NMRG) {
        const int mb = (row * NMRG + t) * MCAP;
        int B = 0;
        for (int tt = t * LPM; tt < t * LPM + LPM; tt++) {
            int nbt = g_anb[row * PBT + tt];
            const int bb = (row * PBT + tt) * BPT;
            for (int b = 0; b < nbt; b++) {
                double cs = g_asum[bb + b];
                int cc = g_acnt[bb + b];
                while (B > 0 && g_m1s[mb + B - 1] * (double)cc < cs * (double)g_m1c[mb + B - 1]) {
                    cs += g_m1s[mb + B - 1]; cc += g_m1c[mb + B - 1]; B--;
                }
                g_m1s[mb + B] = cs; g_m1c[mb + B] = cc; B++;
            }
        }
        g_m1n[row * NMRG + t] = B;
    }
    __syncthreads();

    // Final merge + ends/means
    if (t == 0) {
        const int fb = row * NBIN;
        int B = 0;
        for (int m = 0; m < NMRG; m++) {
            int nm = g_m1n[row * NMRG + m];
            const int mb = (row * NMRG + m) * MCAP;
            for (int b = 0; b < nm; b++) {
                double cs = g_m1s[mb + b];
                int cc = g_m1c[mb + b];
                while (B > 0 && g_fs[fb + B - 1] * (double)cc < cs * (double)g_fc[fb + B - 1]) {
                    cs += g_fs[fb + B - 1]; cc += g_fc[fb + B - 1]; B--;
                }
                g_fs[fb + B] = cs; g_fc[fb + B] = cc; B++;
            }
        }
        int e = 0;
        for (int b = 0; b < B; b++) {
            e += g_fc[fb + b];
            g_fe[fb + b] = e;
            g_fs[fb + b] = g_fs[fb + b] / (double)g_fc[fb + b];  // -> mean
        }
        g_B[row] = B;
    }
    __syncthreads();

    // Bucket -> block-mean map: one binary search per nonempty bucket (8K total)
    {
        const int fb = row * NBIN;
        const int B = g_B[row];
        #pragma unroll
        for (int j = 0; j < BPT; j++) {
            if (lcnt[j]) {
                int p = (int)lpre[j];
                int loB = 0, hiB = B;
                while (loB < hiB) {
                    int mid = (loB + hiB) >> 1;
                    if (g_fe[fb + mid] > p) hiB = mid; else loB = mid + 1;
                }
                bmean[b0 + j] = g_fs[fb + loB];
            }
        }
    }
}

// ---------------- transpose + rank: fully coalesced in and out ---------------
// Block handles 256 docs x 16 rows. Loads transposed sims via smem, writes
// row-major sims and ranks coalesced.
__global__ __launch_bounds__(256) void rankT_kernel(
    const float* __restrict__ simt, const double* __restrict__ bmean,
    float* __restrict__ sims, float* __restrict__ ranks)
{
    __shared__ float st[QN][257];
    const int t = threadIdx.x;
    const int d0 = blockIdx.x * 256;
    const int doc = d0 + t;

    if (doc < N) {
        const uint4* p4 = reinterpret_cast<const uint4*>(simt + (size_t)doc * QN);
        #pragma unroll
        for (int j = 0; j < 4; j++) {
            uint4 v = p4[j];
            st[j*4+0][t] = __uint_as_float(v.x);
            st[j*4+1][t] = __uint_as_float(v.y);
            st[j*4+2][t] = __uint_as_float(v.z);
            st[j*4+3][t] = __uint_as_float(v.w);
        }
    }
    __syncthreads();

    if (doc >= N) return;
    #pragma unroll
    for (int r = 0; r < QN; r++) {
        float sim = st[r][t];
        unsigned u = __float_as_uint(sim);
        unsigned bin = ((unsigned)r << BINBITS) | (ord_of(u) >> (32 - BINBITS));
        double mean = bmean[bin];
        float z = sim * -10.0f;
        int gi = r * N + doc;
        sims[gi] = sim;
        ranks[gi] = (float)((double)z - mean);
    }
}

// ---------------- launch -----------------------------------------------------
extern "C" void kernel_launch(void* const* d_in, const int* in_sizes, int n_in,
                              void* d_out, int out_size)
{
    const float* q = (const float*)d_in[0];
    const float* c = (const float*)d_in[1];
    float* out = (float*)d_out;
    float* sims = out;            // [QN*N]
    float* ranks = out + TOTAL;   // [QN*N]

    void *pc = nullptr, *pz = nullptr, *pm = nullptr, *pst = nullptr;
    cudaGetSymbolAddress(&pc, g_cnt);
    cudaGetSymbolAddress(&pz, g_zsum);
    cudaGetSymbolAddress(&pm, g_bmean);
    cudaGetSymbolAddress(&pst, g_simt);

    cudaMemsetAsync(pc, 0, QN * NBIN * sizeof(unsigned));
    cudaMemsetAsync(pz, 0, QN * NBIN * sizeof(unsigned long long));

    sim_kernel<<<200, 256>>>(q, c, (float*)pst, (unsigned*)pc,
                             (unsigned long long*)pz);
    pav_bucket_kernel<<<QN, PBT>>>((const unsigned*)pc,
                                   (const unsigned long long*)pz,
                                   (double*)pm);
    rankT_kernel<<<(N + 255) / 256, 256>>>((const float*)pst,
                                           (const double*)pm, sims, ranks);
}